// round 2
// baseline (speedup 1.0000x reference)
#include <cuda_runtime.h>
#include <math.h>

#define B_   32
#define T_   512
#define H_   1024
#define E_   2048
#define S_   128
#define L_   512
#define MTOT (B_*T_)        // 16384 rows
#define UVW  (2*E_+S_)      // 4224

// ---------------- scratch (device globals; no cudaMalloc allowed) ----------------
__device__ float g_xn [(size_t)MTOT*H_];     // 64 MB
__device__ float g_uv [(size_t)MTOT*UVW];    // 277 MB  (u | v | base, silu'd)
__device__ float g_q  [(size_t)MTOT*S_];     // 8 MB
__device__ float g_k  [(size_t)MTOT*S_];     // 8 MB
__device__ float g_ker[(size_t)B_*T_*T_];    // 33.5 MB
__device__ float g_att[(size_t)MTOT*E_];     // 134 MB
__device__ float g_sin[T_*64];
__device__ float g_cos[T_*64];

// ---------------- LayerNorm: one block per row of 1024 ----------------
__global__ __launch_bounds__(256) void ln_kernel(const float* __restrict__ x,
                                                 const float* __restrict__ w,
                                                 const float* __restrict__ b)
{
    size_t row = blockIdx.x;
    int tid = threadIdx.x;
    const float4* xr = (const float4*)(x + row * H_);
    float4 v = xr[tid];
    float s  = v.x + v.y + v.z + v.w;
    float ss = v.x*v.x + v.y*v.y + v.z*v.z + v.w*v.w;
    #pragma unroll
    for (int o = 16; o; o >>= 1) {
        s  += __shfl_xor_sync(0xffffffffu, s,  o);
        ss += __shfl_xor_sync(0xffffffffu, ss, o);
    }
    __shared__ float sh_s[8], sh_ss[8];
    __shared__ float s_mu, s_rs;
    int lane = tid & 31, wid = tid >> 5;
    if (lane == 0) { sh_s[wid] = s; sh_ss[wid] = ss; }
    __syncthreads();
    if (tid == 0) {
        float ts = 0.f, tss = 0.f;
        #pragma unroll
        for (int i = 0; i < 8; i++) { ts += sh_s[i]; tss += sh_ss[i]; }
        float mu  = ts  * (1.f / H_);
        float var = tss * (1.f / H_) - mu * mu;
        s_mu = mu;
        s_rs = rsqrtf(var + 1e-5f);
    }
    __syncthreads();
    float mu = s_mu, rs = s_rs;
    float4 w4 = ((const float4*)w)[tid];
    float4 b4 = ((const float4*)b)[tid];
    float4 o;
    o.x = (v.x - mu) * rs * w4.x + b4.x;
    o.y = (v.y - mu) * rs * w4.y + b4.y;
    o.z = (v.z - mu) * rs * w4.z + b4.z;
    o.w = (v.w - mu) * rs * w4.w + b4.w;
    ((float4*)(g_xn + row * H_))[tid] = o;
}

// ---------------- RoPE trig table: sin/cos of fl32(t * fl32(10000^(j/64))) ----------------
__global__ void trig_kernel()
{
    int i = blockIdx.x * 128 + threadIdx.x;   // 512*64 entries
    int t = i >> 6, j = i & 63;
    float invf = (float)pow(10000.0, (double)j * (1.0 / 64.0)); // correctly-rounded fp32
    float prod = (float)t * invf;                               // fp32 rounding as in reference
    g_sin[i] = (float)sin((double)prod);
    g_cos[i] = (float)cos((double)prod);
}

// ---------------- gamma/beta scale-shift + RoPE -> q, k ----------------
__global__ __launch_bounds__(128) void rope_kernel(const float* __restrict__ gamma,
                                                   const float* __restrict__ beta)
{
    size_t row = blockIdx.x;            // b*T + t
    int t = (int)(row & (T_ - 1));
    int s = threadIdx.x;                // 0..127
    float base = g_uv[row * UVW + 2 * E_ + s];
    __shared__ float pre[2][128];
    pre[0][s] = base * gamma[s]       + beta[s];
    pre[1][s] = base * gamma[128 + s] + beta[128 + s];
    __syncthreads();
    int which = s >> 6, j = s & 63;
    float x1 = pre[which][j], x2 = pre[which][j + 64];
    float sv = g_sin[t * 64 + j], cv = g_cos[t * 64 + j];
    float* dst = which ? g_k : g_q;
    dst[row * S_ + j]      = x1 * cv - x2 * sv;
    dst[row * S_ + j + 64] = x2 * cv + x1 * sv;
}

// ---------------- epilogue functors ----------------
struct EpiSiluUV {
    float* C; const float* bias;
    __device__ void operator()(int bz, int m, int n, float acc) const {
        float v = acc + bias[n];
        C[(size_t)m * UVW + n] = v / (1.f + expf(-v));
    }
};
struct EpiScore {
    float* C; const float* w;
    __device__ void operator()(int bz, int m, int n, float acc) const {
        float s = acc / 11.313708498984761f + w[n - m + (L_ - 1)];
        s = fmaxf(s, 0.f);
        C[(size_t)bz * T_ * T_ + (size_t)m * T_ + n] = s * s;
    }
};
struct EpiMulU {
    float* C; const float* uv;
    __device__ void operator()(int bz, int m, int n, float acc) const {
        size_t row = (size_t)bz * T_ + m;
        C[row * E_ + n] = acc * uv[row * UVW + n];   // gate by u (cols 0..E-1)
    }
};
struct EpiFinal {
    float* C; const float* ob; const float* x;
    __device__ void operator()(int bz, int m, int n, float acc) const {
        size_t idx = (size_t)m * H_ + n;
        C[idx] = acc + ob[n] + x[idx];               // + o_b + shortcut
    }
};

// ---------------- SIMT fp32 GEMM, 128x128 tile, BK=16, 8x8/thread, double-buffered ----------------
// C[m,n] = sum_k A[m,k] * Bop[n,k]
//   BNT=true : B stored [N,K] row-major  (K-contiguous, "NT")
//   BNT=false: B stored [K,N] row-major  (N-contiguous, "NN")
// All of M, N divisible by 128; K divisible by 16 (true for every call site).
template<bool BNT, class Epi>
__global__ __launch_bounds__(256, 2) void gemm128(
    const float* __restrict__ A, int lda, long aStr,
    const float* __restrict__ B, int ldb, long bStr,
    int K, Epi epi)
{
    __shared__ float As[2][16][132];
    __shared__ float Bs[2][16][132];
    int tid = threadIdx.x;
    int bz  = blockIdx.z;
    const float* Ab = A + (size_t)bz * aStr + (size_t)blockIdx.y * 128 * lda;
    const float* Bb;
    if (BNT) Bb = B + (size_t)bz * bStr + (size_t)blockIdx.x * 128 * ldb;
    else     Bb = B + (size_t)bz * bStr + (size_t)blockIdx.x * 128;

    float4 aR[2], bR[2];
    auto ldg = [&](int kt) {
        int k0 = kt * 16;
        #pragma unroll
        for (int i = 0; i < 2; i++) {
            int l = tid + i * 256;
            aR[i] = *(const float4*)(Ab + (size_t)(l >> 2) * lda + k0 + (l & 3) * 4);
            if (BNT)
                bR[i] = *(const float4*)(Bb + (size_t)(l >> 2) * ldb + k0 + (l & 3) * 4);
            else
                bR[i] = *(const float4*)(Bb + (size_t)(k0 + (l >> 5)) * ldb + (l & 31) * 4);
        }
    };
    auto sts = [&](int buf) {
        #pragma unroll
        for (int i = 0; i < 2; i++) {
            int l = tid + i * 256;
            int r = l >> 2, c = (l & 3) * 4;
            As[buf][c + 0][r] = aR[i].x; As[buf][c + 1][r] = aR[i].y;
            As[buf][c + 2][r] = aR[i].z; As[buf][c + 3][r] = aR[i].w;
            if (BNT) {
                Bs[buf][c + 0][r] = bR[i].x; Bs[buf][c + 1][r] = bR[i].y;
                Bs[buf][c + 2][r] = bR[i].z; Bs[buf][c + 3][r] = bR[i].w;
            } else {
                *(float4*)&Bs[buf][l >> 5][(l & 31) * 4] = bR[i];
            }
        }
    };

    float acc[8][8];
    #pragma unroll
    for (int i = 0; i < 8; i++)
        #pragma unroll
        for (int j = 0; j < 8; j++) acc[i][j] = 0.f;

    int tm = (tid >> 4) * 8, tn = (tid & 15) * 8;
    int KT = K / 16;
    ldg(0); sts(0); __syncthreads();
    for (int kt = 0; kt < KT; ++kt) {
        int cur = kt & 1;
        if (kt + 1 < KT) ldg(kt + 1);
        #pragma unroll
        for (int kk = 0; kk < 16; kk++) {
            float a[8], b[8];
            *(float4*)(a)     = *(const float4*)&As[cur][kk][tm];
            *(float4*)(a + 4) = *(const float4*)&As[cur][kk][tm + 4];
            *(float4*)(b)     = *(const float4*)&Bs[cur][kk][tn];
            *(float4*)(b + 4) = *(const float4*)&Bs[cur][kk][tn + 4];
            #pragma unroll
            for (int i = 0; i < 8; i++)
                #pragma unroll
                for (int j = 0; j < 8; j++)
                    acc[i][j] = fmaf(a[i], b[j], acc[i][j]);
        }
        if (kt + 1 < KT) { sts(cur ^ 1); __syncthreads(); }
    }
    int m0 = blockIdx.y * 128 + tm, n0 = blockIdx.x * 128 + tn;
    #pragma unroll
    for (int i = 0; i < 8; i++)
        #pragma unroll
        for (int j = 0; j < 8; j++)
            epi(bz, m0 + i, n0 + j, acc[i][j]);
}

// ---------------- host launcher ----------------
extern "C" void kernel_launch(void* const* d_in, const int* in_sizes, int n_in,
                              void* d_out, int out_size)
{
    const float* x     = (const float*)d_in[0];
    const float* ln_w  = (const float*)d_in[1];
    const float* ln_b  = (const float*)d_in[2];
    const float* uv_w  = (const float*)d_in[3];
    const float* uv_b  = (const float*)d_in[4];
    const float* gamma = (const float*)d_in[5];
    const float* beta  = (const float*)d_in[6];
    const float* w     = (const float*)d_in[7];
    const float* o_w   = (const float*)d_in[8];
    const float* o_b   = (const float*)d_in[9];
    float* out = (float*)d_out;

    float *p_xn, *p_uv, *p_q, *p_k, *p_ker, *p_att;
    cudaGetSymbolAddress((void**)&p_xn,  g_xn);
    cudaGetSymbolAddress((void**)&p_uv,  g_uv);
    cudaGetSymbolAddress((void**)&p_q,   g_q);
    cudaGetSymbolAddress((void**)&p_k,   g_k);
    cudaGetSymbolAddress((void**)&p_ker, g_ker);
    cudaGetSymbolAddress((void**)&p_att, g_att);

    // 1) LayerNorm
    ln_kernel<<<MTOT, 256>>>(x, ln_w, ln_b);
    // 2) RoPE trig table (deterministic, recomputed every call)
    trig_kernel<<<(T_ * 64) / 128, 128>>>();
    // 3) uv = silu(xn @ uv_w^T + uv_b)   [16384 x 4224 x 1024], NT
    gemm128<true><<<dim3(UVW / 128, MTOT / 128, 1), 256>>>(
        p_xn, H_, 0L, uv_w, H_, 0L, H_, EpiSiluUV{p_uv, uv_b});
    // 4) q,k from base (gamma/beta + rope)
    rope_kernel<<<MTOT, 128>>>(gamma, beta);
    // 5) kernel = relu(q@k^T / sqrt(S) + bias)^2   per batch, NT
    gemm128<true><<<dim3(T_ / 128, T_ / 128, B_), 256>>>(
        p_q, S_, (long)T_ * S_, p_k, S_, (long)T_ * S_, S_, EpiScore{p_ker, w});
    // 6) att = u * (kernel @ v)   per batch, NN (v is [K=T, N=E] with row stride UVW)
    gemm128<false><<<dim3(E_ / 128, T_ / 128, B_), 256>>>(
        p_ker, T_, (long)T_ * T_, p_uv + E_, UVW, (long)T_ * UVW, T_, EpiMulU{p_att, p_uv});
    // 7) out = att @ o_w^T + o_b + x   [16384 x 1024 x 2048], NT
    gemm128<true><<<dim3(H_ / 128, MTOT / 128, 1), 256>>>(
        p_att, E_, 0L, o_w, E_, 0L, E_, EpiFinal{out, o_b, x});
}

// round 8
// speedup vs baseline: 3.1493x; 3.1493x over previous
#include <cuda_runtime.h>
#include <math.h>
#include <stdint.h>

#define B_   32
#define T_   512
#define H_   1024
#define E_   2048
#define S_   128
#define L_   512
#define MTOT (B_*T_)        // 16384
#define UVW  (2*E_+S_)      // 4224

// GEMM tiling: block 128x128, BK=32, 4 warps (2x2) of 64x64 each.
#define BK 32
#define ROWSTRIDE 36                      // floats; 144B rows, conflict-free & 16B-aligned
#define TILE_FLOATS (128*ROWSTRIDE)       // per operand per stage
#define STAGE_FLOATS (2*TILE_FLOATS)      // A + B
#define SMEM_BYTES (2*STAGE_FLOATS*4)     // double buffer = 73728 B

// ---------------- scratch ----------------
__device__ float g_xn [(size_t)MTOT*H_];
__device__ float g_uv [(size_t)MTOT*UVW];
__device__ float g_q  [(size_t)MTOT*S_];
__device__ float g_k  [(size_t)MTOT*S_];
__device__ float g_ker[(size_t)B_*T_*T_];
__device__ float g_att[(size_t)MTOT*E_];
__device__ float g_vT [(size_t)B_*E_*T_];
__device__ float g_wuv[(size_t)UVW*H_];
__device__ float g_owT[(size_t)H_*E_];
__device__ float g_sin[T_*64];
__device__ float g_cos[T_*64];

// ---------------- helpers ----------------
__device__ __forceinline__ uint32_t smem_u32(const void* p){
    uint32_t a;
    asm("{ .reg .u64 t; cvta.to.shared.u64 t, %1; cvt.u32.u64 %0, t; }" : "=r"(a) : "l"(p));
    return a;
}
__device__ __forceinline__ float rtf32(float x){
    uint32_t u;
    asm("cvt.rna.tf32.f32 %0, %1;" : "=r"(u) : "f"(x));
    return __uint_as_float(u);
}
__device__ __forceinline__ void cpasync16(uint32_t dst, const void* src){
    asm volatile("cp.async.cg.shared.global [%0], [%1], 16;" :: "r"(dst), "l"(src));
}
__device__ __forceinline__ void mma_tf32(float* d, const uint32_t* a, const uint32_t* b){
    asm volatile(
        "mma.sync.aligned.m16n8k8.row.col.f32.tf32.tf32.f32 "
        "{%0,%1,%2,%3}, {%4,%5,%6,%7}, {%8,%9}, {%0,%1,%2,%3};"
        : "+f"(d[0]), "+f"(d[1]), "+f"(d[2]), "+f"(d[3])
        : "r"(a[0]), "r"(a[1]), "r"(a[2]), "r"(a[3]), "r"(b[0]), "r"(b[1]));
}

// ---------------- LayerNorm (tf32-rounded output) ----------------
__global__ __launch_bounds__(256) void ln_kernel(const float* __restrict__ x,
                                                 const float* __restrict__ w,
                                                 const float* __restrict__ b)
{
    size_t row = blockIdx.x;
    int tid = threadIdx.x;
    const float4* xr = (const float4*)(x + row * H_);
    float4 v = xr[tid];
    float s  = v.x + v.y + v.z + v.w;
    float ss = v.x*v.x + v.y*v.y + v.z*v.z + v.w*v.w;
    #pragma unroll
    for (int o = 16; o; o >>= 1) {
        s  += __shfl_xor_sync(0xffffffffu, s,  o);
        ss += __shfl_xor_sync(0xffffffffu, ss, o);
    }
    __shared__ float sh_s[8], sh_ss[8];
    __shared__ float s_mu, s_rs;
    int lane = tid & 31, wid = tid >> 5;
    if (lane == 0) { sh_s[wid] = s; sh_ss[wid] = ss; }
    __syncthreads();
    if (tid == 0) {
        float ts = 0.f, tss = 0.f;
        #pragma unroll
        for (int i = 0; i < 8; i++) { ts += sh_s[i]; tss += sh_ss[i]; }
        float mu  = ts  * (1.f / H_);
        float var = tss * (1.f / H_) - mu * mu;
        s_mu = mu;
        s_rs = rsqrtf(var + 1e-5f);
    }
    __syncthreads();
    float mu = s_mu, rs = s_rs;
    float4 w4 = ((const float4*)w)[tid];
    float4 b4 = ((const float4*)b)[tid];
    float4 o;
    o.x = rtf32((v.x - mu) * rs * w4.x + b4.x);
    o.y = rtf32((v.y - mu) * rs * w4.y + b4.y);
    o.z = rtf32((v.z - mu) * rs * w4.z + b4.z);
    o.w = rtf32((v.w - mu) * rs * w4.w + b4.w);
    ((float4*)(g_xn + row * H_))[tid] = o;
}

// ---------------- RoPE trig table ----------------
__global__ void trig_kernel()
{
    int i = blockIdx.x * 128 + threadIdx.x;
    int t = i >> 6, j = i & 63;
    float invf = (float)pow(10000.0, (double)j * (1.0 / 64.0));
    float prod = (float)t * invf;
    g_sin[i] = (float)sin((double)prod);
    g_cos[i] = (float)cos((double)prod);
}

// ---------------- gamma/beta + RoPE -> q, k (tf32-rounded) ----------------
__global__ __launch_bounds__(128) void rope_kernel(const float* __restrict__ gamma,
                                                   const float* __restrict__ beta)
{
    size_t row = blockIdx.x;
    int t = (int)(row & (T_ - 1));
    int s = threadIdx.x;
    float base = g_uv[row * UVW + 2 * E_ + s];
    __shared__ float pre[2][128];
    pre[0][s] = base * gamma[s]       + beta[s];
    pre[1][s] = base * gamma[128 + s] + beta[128 + s];
    __syncthreads();
    int which = s >> 6, j = s & 63;
    float x1 = pre[which][j], x2 = pre[which][j + 64];
    float sv = g_sin[t * 64 + j], cv = g_cos[t * 64 + j];
    float* dst = which ? g_k : g_q;
    dst[row * S_ + j]      = rtf32(x1 * cv - x2 * sv);
    dst[row * S_ + j + 64] = rtf32(x2 * cv + x1 * sv);
}

// ---------------- tf32 round-copy for weights ----------------
__global__ __launch_bounds__(256) void round4(const float4* __restrict__ s,
                                              float4* __restrict__ d, int n4)
{
    int i = blockIdx.x * 256 + threadIdx.x;
    if (i < n4) {
        float4 v = s[i];
        v.x = rtf32(v.x); v.y = rtf32(v.y); v.z = rtf32(v.z); v.w = rtf32(v.w);
        d[i] = v;
    }
}

// ---------------- v transpose (per batch), tf32-rounded ----------------
__global__ __launch_bounds__(256) void vT_kernel()
{
    __shared__ float t[32][33];
    int b  = blockIdx.z;
    int e0 = blockIdx.x * 32, t0 = blockIdx.y * 32;
    int tx = threadIdx.x & 31, ty = threadIdx.x >> 5;
    #pragma unroll
    for (int i = 0; i < 32; i += 8)
        t[ty + i][tx] = g_uv[((size_t)(b * T_ + t0 + ty + i)) * UVW + E_ + e0 + tx];
    __syncthreads();
    #pragma unroll
    for (int i = 0; i < 32; i += 8)
        g_vT[((size_t)b * E_ + e0 + ty + i) * T_ + t0 + tx] = rtf32(t[tx][ty + i]);
}

// ---------------- epilogue functors: write 2 adjacent cols (row, col..col+1) ----------------
struct EpiSiluUV {
    float* C; const float* bias;
    __device__ void operator()(int, int m, int n, float v0, float v1) const {
        float a = v0 + bias[n], b = v1 + bias[n + 1];
        float2 o = make_float2(a / (1.f + expf(-a)), b / (1.f + expf(-b)));
        *(float2*)(C + (size_t)m * UVW + n) = o;
    }
};
struct EpiScore {
    float* C; const float* w;
    __device__ void operator()(int bz, int m, int n, float v0, float v1) const {
        float a = v0 * 0.08838834764831845f + w[n - m + (L_ - 1)];
        float b = v1 * 0.08838834764831845f + w[n + 1 - m + (L_ - 1)];
        a = fmaxf(a, 0.f); b = fmaxf(b, 0.f);
        float2 o = make_float2(rtf32(a * a), rtf32(b * b));
        *(float2*)(C + ((size_t)bz * T_ + m) * T_ + n) = o;
    }
};
struct EpiMulU {
    float* C; const float* uv;
    __device__ void operator()(int bz, int m, int n, float v0, float v1) const {
        size_t row = (size_t)bz * T_ + m;
        float2 u = *(const float2*)(uv + row * UVW + n);
        float2 o = make_float2(rtf32(v0 * u.x), rtf32(v1 * u.y));
        *(float2*)(C + row * E_ + n) = o;
    }
};
struct EpiFinal {
    float* C; const float* ob; const float* x;
    __device__ void operator()(int, int m, int n, float v0, float v1) const {
        size_t idx = (size_t)m * H_ + n;
        float2 xs = *(const float2*)(x + idx);
        float2 o = make_float2(v0 + ob[n] + xs.x, v1 + ob[n + 1] + xs.y);
        *(float2*)(C + idx) = o;
    }
};

// ---------------- tf32 mma.sync GEMM: C[m,n] = sum_k A[m,k]*B[n,k] ----------------
// Block 128x128, BK=32, 4 warps (2x2), warp tile 64x64 (4x8 m16n8k8 atoms).
// A, B both [rows][K] row-major (NT). M%128==0, N%128==0, K%32==0.
template<class Epi>
__global__ __launch_bounds__(128, 2) void gemm_mma(
    const float* __restrict__ A, long long aStr, int lda,
    const float* __restrict__ B, long long bStr, int ldb,
    int K, Epi epi)
{
    extern __shared__ float sm[];
    int tid  = threadIdx.x;
    int bz   = blockIdx.z;
    int wid  = tid >> 5, lane = tid & 31;
    int g    = lane >> 2, tg = lane & 3;
    int m0w  = (wid >> 1) * 64;      // warp row offset in tile
    int n0w  = (wid & 1) * 64;       // warp col offset in tile

    const float* Ab = A + (size_t)bz * aStr + (size_t)blockIdx.y * 128 * lda;
    const float* Bb = B + (size_t)bz * bStr + (size_t)blockIdx.x * 128 * ldb;

    auto load_stage = [&](int buf, int kt) {
        float* As  = sm + buf * STAGE_FLOATS;
        float* Bs  = As + TILE_FLOATS;
        uint32_t asb = smem_u32(As), bsb = smem_u32(Bs);
        const float* Ak = Ab + kt * BK;
        const float* Bk = Bb + kt * BK;
        #pragma unroll
        for (int i = 0; i < 8; i++) {
            int idx = tid + i * 128;            // 0..1023
            int r = idx >> 3, kb = idx & 7;     // row, 16B sub-block
            cpasync16(asb + (r * ROWSTRIDE + kb * 4) * 4, Ak + (size_t)r * lda + kb * 4);
        }
        #pragma unroll
        for (int i = 0; i < 8; i++) {
            int idx = tid + i * 128;
            int r = idx >> 3, kb = idx & 7;
            cpasync16(bsb + (r * ROWSTRIDE + kb * 4) * 4, Bk + (size_t)r * ldb + kb * 4);
        }
        asm volatile("cp.async.commit_group;" ::: "memory");
    };

    float acc[4][8][4];
    #pragma unroll
    for (int i = 0; i < 4; i++)
        #pragma unroll
        for (int j = 0; j < 8; j++)
            #pragma unroll
            for (int c = 0; c < 4; c++) acc[i][j][c] = 0.f;

    int KT = K / BK;
    load_stage(0, 0);
    for (int kt = 0; kt < KT; kt++) {
        int cur = kt & 1;
        asm volatile("cp.async.wait_group 0;" ::: "memory");
        __syncthreads();
        if (kt + 1 < KT) load_stage(cur ^ 1, kt + 1);

        const float* As = sm + cur * STAGE_FLOATS;
        const float* Bs = As + TILE_FLOATS;
        #pragma unroll
        for (int kk = 0; kk < 4; kk++) {
            int k0 = kk * 8;
            uint32_t af[4][4];
            #pragma unroll
            for (int ma = 0; ma < 4; ma++) {
                const float* ap = As + (m0w + ma * 16 + g) * ROWSTRIDE + k0;
                af[ma][0] = __float_as_uint(ap[tg]);
                af[ma][1] = __float_as_uint(ap[8 * ROWSTRIDE + tg]);
                af[ma][2] = __float_as_uint(ap[tg + 4]);
                af[ma][3] = __float_as_uint(ap[8 * ROWSTRIDE + tg + 4]);
            }
            uint32_t bf[8][2];
            #pragma unroll
            for (int nb = 0; nb < 8; nb++) {
                const float* bp = Bs + (n0w + nb * 8 + g) * ROWSTRIDE + k0;
                bf[nb][0] = __float_as_uint(bp[tg]);
                bf[nb][1] = __float_as_uint(bp[tg + 4]);
            }
            #pragma unroll
            for (int ma = 0; ma < 4; ma++)
                #pragma unroll
                for (int nb = 0; nb < 8; nb++)
                    mma_tf32(acc[ma][nb], af[ma], bf[nb]);
        }
        __syncthreads();
    }

    int mBase = blockIdx.y * 128 + m0w + g;
    int nBase = blockIdx.x * 128 + n0w + tg * 2;
    #pragma unroll
    for (int ma = 0; ma < 4; ma++)
        #pragma unroll
        for (int nb = 0; nb < 8; nb++) {
            int r0 = mBase + ma * 16;
            int c0 = nBase + nb * 8;
            epi(bz, r0,     c0, acc[ma][nb][0], acc[ma][nb][1]);
            epi(bz, r0 + 8, c0, acc[ma][nb][2], acc[ma][nb][3]);
        }
}

// ---------------- host launcher ----------------
extern "C" void kernel_launch(void* const* d_in, const int* in_sizes, int n_in,
                              void* d_out, int out_size)
{
    const float* x     = (const float*)d_in[0];
    const float* ln_w  = (const float*)d_in[1];
    const float* ln_b  = (const float*)d_in[2];
    const float* uv_w  = (const float*)d_in[3];
    const float* uv_b  = (const float*)d_in[4];
    const float* gamma = (const float*)d_in[5];
    const float* beta  = (const float*)d_in[6];
    const float* w     = (const float*)d_in[7];
    const float* o_w   = (const float*)d_in[8];
    const float* o_b   = (const float*)d_in[9];
    float* out = (float*)d_out;

    float *p_xn, *p_uv, *p_q, *p_k, *p_ker, *p_att, *p_vT, *p_wuv, *p_owT;
    cudaGetSymbolAddress((void**)&p_xn,  g_xn);
    cudaGetSymbolAddress((void**)&p_uv,  g_uv);
    cudaGetSymbolAddress((void**)&p_q,   g_q);
    cudaGetSymbolAddress((void**)&p_k,   g_k);
    cudaGetSymbolAddress((void**)&p_ker, g_ker);
    cudaGetSymbolAddress((void**)&p_att, g_att);
    cudaGetSymbolAddress((void**)&p_vT,  g_vT);
    cudaGetSymbolAddress((void**)&p_wuv, g_wuv);
    cudaGetSymbolAddress((void**)&p_owT, g_owT);

    cudaFuncSetAttribute(gemm_mma<EpiSiluUV>, cudaFuncAttributeMaxDynamicSharedMemorySize, SMEM_BYTES);
    cudaFuncSetAttribute(gemm_mma<EpiScore>,  cudaFuncAttributeMaxDynamicSharedMemorySize, SMEM_BYTES);
    cudaFuncSetAttribute(gemm_mma<EpiMulU>,   cudaFuncAttributeMaxDynamicSharedMemorySize, SMEM_BYTES);
    cudaFuncSetAttribute(gemm_mma<EpiFinal>,  cudaFuncAttributeMaxDynamicSharedMemorySize, SMEM_BYTES);

    // 1) LayerNorm
    ln_kernel<<<MTOT, 256>>>(x, ln_w, ln_b);
    // 2) trig table
    trig_kernel<<<(T_ * 64) / 128, 128>>>();
    // 3) tf32-rounded weight copies
    round4<<<((UVW * H_) / 4 + 255) / 256, 256>>>((const float4*)uv_w, (float4*)p_wuv, (UVW * H_) / 4);
    round4<<<((H_ * E_) / 4 + 255) / 256, 256>>>((const float4*)o_w, (float4*)p_owT, (H_ * E_) / 4);
    // 4) uv = silu(xn @ uv_w^T + uv_b)  [16384 x 4224 x 1024]
    gemm_mma<EpiSiluUV><<<dim3(UVW / 128, MTOT / 128, 1), 128, SMEM_BYTES>>>(
        p_xn, 0LL, H_, p_wuv, 0LL, H_, H_, EpiSiluUV{p_uv, uv_b});
    // 5) q,k
    rope_kernel<<<MTOT, 128>>>(gamma, beta);
    // 6) v^T per batch
    vT_kernel<<<dim3(E_ / 32, T_ / 32, B_), 256>>>();
    // 7) kernel = relu(q@k^T/sqrt(S)+bias)^2  per batch [512x512x128]
    gemm_mma<EpiScore><<<dim3(T_ / 128, T_ / 128, B_), 128, SMEM_BYTES>>>(
        p_q, (long long)T_ * S_, S_, p_k, (long long)T_ * S_, S_, S_, EpiScore{p_ker, w});
    // 8) att = u * (kernel @ v)  per batch [512x2048x512]
    gemm_mma<EpiMulU><<<dim3(E_ / 128, T_ / 128, B_), 128, SMEM_BYTES>>>(
        p_ker, (long long)T_ * T_, T_, p_vT, (long long)E_ * T_, T_, T_, EpiMulU{p_att, p_uv});
    // 9) out = att @ o_w^T + o_b + x  [16384 x 1024 x 2048]
    gemm_mma<EpiFinal><<<dim3(H_ / 128, MTOT / 128, 1), 128, SMEM_BYTES>>>(
        p_att, 0LL, E_, p_owT, 0LL, E_, E_, EpiFinal{out, o_b, x});
}